// round 12
// baseline (speedup 1.0000x reference)
#include <cuda_runtime.h>
#include <cuda_fp16.h>
#include <math.h>
#include <stdint.h>

#define D_MODEL 2048
#define NEXP    128
#define BM      128
#define KC      64
#define NKC     (D_MODEL / KC)    // 32
#define NTHREADS 512
#define TOPK    8

#define SAW    72                   // smem stride in halves (144B rows -> conflict-free ldmatrix)
#define TILEB  (128 * SAW * 2)      // 18432 B per tile
#define BUFB   (4 * TILEB)          // A_hi, A_lo, B_hi, B_lo = 73728 B
#define SMEM_REQ (2 * BUFB)         // 147456 B
#define LS_W   132

#define SX 64.0f
#define SW 256.0f
#define DESCALE 6.103515625e-05f    // 2^-14 exact

__device__ __half WHg[NEXP * D_MODEL];
__device__ __half WLg[NEXP * D_MODEL];

__device__ __forceinline__ uint32_t smem_u32(const void* p) {
    uint32_t a;
    asm("{ .reg .u64 t; cvta.to.shared.u64 t, %1; cvt.u32.u64 %0, t; }" : "=r"(a) : "l"(p));
    return a;
}
__device__ __forceinline__ void ldmx4(uint32_t& r0, uint32_t& r1, uint32_t& r2, uint32_t& r3,
                                      uint32_t addr) {
    asm volatile("ldmatrix.sync.aligned.m8n8.x4.shared.b16 {%0,%1,%2,%3}, [%4];"
                 : "=r"(r0), "=r"(r1), "=r"(r2), "=r"(r3) : "r"(addr));
}
__device__ __forceinline__ void mma16816(float* d, const uint32_t* a, uint32_t b0, uint32_t b1) {
    asm volatile(
        "mma.sync.aligned.m16n8k16.row.col.f32.f16.f16.f32 "
        "{%0,%1,%2,%3}, {%4,%5,%6,%7}, {%8,%9}, {%0,%1,%2,%3};"
        : "+f"(d[0]), "+f"(d[1]), "+f"(d[2]), "+f"(d[3])
        : "r"(a[0]), "r"(a[1]), "r"(a[2]), "r"(a[3]), "r"(b0), "r"(b1));
}
__device__ __forceinline__ void cpasync16(uint32_t saddr, const void* gptr) {
    asm volatile("cp.async.ca.shared.global [%0], [%1], 16;" :: "r"(saddr), "l"(gptr) : "memory");
}

__device__ __forceinline__ void split4(float4 v, float s, uint2& hi, uint2& lo) {
    float a = v.x * s, b = v.y * s, c = v.z * s, d = v.w * s;
    __half2 h01 = __floats2half2_rn(a, b);
    __half2 h23 = __floats2half2_rn(c, d);
    float2 f01 = __half22float2(h01);
    float2 f23 = __half22float2(h23);
    __half2 l01 = __floats2half2_rn(a - f01.x, b - f01.y);
    __half2 l23 = __floats2half2_rn(c - f23.x, d - f23.y);
    hi.x = *reinterpret_cast<uint32_t*>(&h01);
    hi.y = *reinterpret_cast<uint32_t*>(&h23);
    lo.x = *reinterpret_cast<uint32_t*>(&l01);
    lo.y = *reinterpret_cast<uint32_t*>(&l23);
}

// ---- kernel 0: split W once ----
__global__ void wsplit_kernel(const float* __restrict__ W) {
    int idx = blockIdx.x * blockDim.x + threadIdx.x;   // over NEXP*D_MODEL/4
    float4 v = reinterpret_cast<const float4*>(W)[idx];
    uint2 h, l;
    split4(v, SW, h, l);
    reinterpret_cast<uint2*>(WHg)[idx] = h;
    reinterpret_cast<uint2*>(WLg)[idx] = l;
}

__global__ __launch_bounds__(NTHREADS, 1)
void moe_router_kernel(const float* __restrict__ X,
                       const float* __restrict__ BIAS,
                       float* __restrict__ OUTW,
                       float* __restrict__ OUTI,
                       int writeIdx, int Ntok)
{
    extern __shared__ char sraw[];
    const uint32_t sbase = smem_u32(sraw);

    const int tid  = threadIdx.x;
    const int wid  = tid >> 5;
    const int lane = tid & 31;
    const int bm0  = blockIdx.x * BM;

    const int wm = wid >> 2;
    const int wn = wid & 3;

    const uint32_t aoff = (uint32_t)(((lane & 15) * SAW + (lane >> 4) * 8) * 2);
    const uint32_t boff = (uint32_t)((((lane & 7) + ((lane >> 4) << 3)) * SAW) * 2
                                     + ((lane >> 3) & 1) * 16);

    // A staging: 128 rows x 16 float4 = 2048 float4 / 512 thr = 4 per thread
    int rA[4], cA[4];
#pragma unroll
    for (int p = 0; p < 4; ++p) {
        int idx = tid + p * NTHREADS;
        rA[p] = idx >> 4;
        cA[p] = (idx & 15) * 4;
    }
    // B staging (cp.async): 128 rows x 64 halves; per thread 2 chunks of 8 halves per precision
    const int rB = tid >> 2;
    const int cB = (tid & 3) * 8;   // halves: 0,8,16,24 ; plus +32 for the second chunk

    float acc[2][4][4];
#pragma unroll
    for (int i = 0; i < 2; ++i)
#pragma unroll
        for (int j = 0; j < 4; ++j)
#pragma unroll
            for (int q = 0; q < 4; ++q)
                acc[i][j][q] = 0.f;

    // ---- prologue: stage chunk 0 ----
    float4 axr[4];
#pragma unroll
    for (int p = 0; p < 4; ++p) {
        int row = bm0 + rA[p];
        axr[p] = (row < Ntok)
            ? *reinterpret_cast<const float4*>(X + (size_t)row * D_MODEL + cA[p])
            : make_float4(0.f, 0.f, 0.f, 0.f);
    }
    {
        char* AH = sraw;
        char* AL = sraw + TILEB;
#pragma unroll
        for (int p = 0; p < 4; ++p) {
            uint32_t off = (uint32_t)(rA[p] * SAW + cA[p]) * 2;
            uint2 h, l;
            split4(axr[p], SX, h, l);
            *reinterpret_cast<uint2*>(AH + off) = h;
            *reinterpret_cast<uint2*>(AL + off) = l;
        }
        uint32_t bdst = sbase + 2 * TILEB + (uint32_t)(rB * SAW + cB) * 2;
        const __half* gH = WHg + (size_t)rB * D_MODEL + cB;
        const __half* gL = WLg + (size_t)rB * D_MODEL + cB;
        cpasync16(bdst,              gH);
        cpasync16(bdst + 64,         gH + 32);
        cpasync16(bdst + TILEB,      gL);
        cpasync16(bdst + TILEB + 64, gL + 32);
        asm volatile("cp.async.commit_group;" ::: "memory");
        asm volatile("cp.async.wait_group 0;" ::: "memory");
    }
    __syncthreads();

    for (int c = 0; c < NKC; ++c) {
        const int buf = c & 1;
        // prefetch next A chunk into registers (overlaps MMAs)
        if (c + 1 < NKC) {
            const int k0 = (c + 1) * KC;
#pragma unroll
            for (int p = 0; p < 4; ++p) {
                int row = bm0 + rA[p];
                axr[p] = (row < Ntok)
                    ? *reinterpret_cast<const float4*>(X + (size_t)row * D_MODEL + k0 + cA[p])
                    : make_float4(0.f, 0.f, 0.f, 0.f);
            }
        }

        const uint32_t bufA = sbase + buf * BUFB;
#pragma unroll
        for (int ks = 0; ks < KC / 16; ++ks) {
            const uint32_t kb = ks * 32;
            uint32_t aH[2][4], aL[2][4];
#pragma unroll
            for (int mt = 0; mt < 2; ++mt) {
                uint32_t ab = bufA + (uint32_t)((wm * 32 + mt * 16) * SAW * 2) + aoff + kb;
                ldmx4(aH[mt][0], aH[mt][1], aH[mt][2], aH[mt][3], ab);
                ldmx4(aL[mt][0], aL[mt][1], aL[mt][2], aL[mt][3], ab + TILEB);
            }
            uint32_t bh[4][2], bl[4][2];
#pragma unroll
            for (int pr = 0; pr < 2; ++pr) {
                uint32_t bb = bufA + 2 * TILEB
                            + (uint32_t)((wn * 32 + pr * 16) * SAW * 2) + boff + kb;
                ldmx4(bh[pr * 2][0], bh[pr * 2][1], bh[pr * 2 + 1][0], bh[pr * 2 + 1][1], bb);
                ldmx4(bl[pr * 2][0], bl[pr * 2][1], bl[pr * 2 + 1][0], bl[pr * 2 + 1][1], bb + TILEB);
            }
#pragma unroll
            for (int ng = 0; ng < 4; ++ng)
#pragma unroll
                for (int mt = 0; mt < 2; ++mt)
                    mma16816(acc[mt][ng], aH[mt], bh[ng][0], bh[ng][1]);
#pragma unroll
            for (int ng = 0; ng < 4; ++ng)
#pragma unroll
                for (int mt = 0; mt < 2; ++mt)
                    mma16816(acc[mt][ng], aH[mt], bl[ng][0], bl[ng][1]);
#pragma unroll
            for (int ng = 0; ng < 4; ++ng)
#pragma unroll
                for (int mt = 0; mt < 2; ++mt)
                    mma16816(acc[mt][ng], aL[mt], bh[ng][0], bh[ng][1]);
        }

        if (c + 1 < NKC) {
            // split prefetched A in registers BEFORE the barrier
            uint2 ah[4], al[4];
#pragma unroll
            for (int p = 0; p < 4; ++p)
                split4(axr[p], SX, ah[p], al[p]);

            char* db = sraw + ((c + 1) & 1) * BUFB;
            __syncthreads();
            char* nAH = db;
            char* nAL = db + TILEB;
#pragma unroll
            for (int p = 0; p < 4; ++p) {
                uint32_t off = (uint32_t)(rA[p] * SAW + cA[p]) * 2;
                *reinterpret_cast<uint2*>(nAH + off) = ah[p];
                *reinterpret_cast<uint2*>(nAL + off) = al[p];
            }
            const int k0 = (c + 1) * KC;
            uint32_t bdst = sbase + ((c + 1) & 1) * BUFB + 2 * TILEB
                          + (uint32_t)(rB * SAW + cB) * 2;
            const __half* gH = WHg + (size_t)rB * D_MODEL + k0 + cB;
            const __half* gL = WLg + (size_t)rB * D_MODEL + k0 + cB;
            cpasync16(bdst,              gH);
            cpasync16(bdst + 64,         gH + 32);
            cpasync16(bdst + TILEB,      gL);
            cpasync16(bdst + TILEB + 64, gL + 32);
            asm volatile("cp.async.commit_group;" ::: "memory");
            asm volatile("cp.async.wait_group 0;" ::: "memory");
            __syncthreads();
        }
    }

    // ---- logits to smem (descaled) ----
    __syncthreads();
    float* Ls = reinterpret_cast<float*>(sraw);
    {
        const int g  = lane >> 2;
        const int t2 = (lane & 3) * 2;
#pragma unroll
        for (int mt = 0; mt < 2; ++mt) {
            int row = wm * 32 + mt * 16 + g;
#pragma unroll
            for (int ng = 0; ng < 4; ++ng) {
                int col = wn * 32 + ng * 8 + t2;
                *reinterpret_cast<float2*>(&Ls[row * LS_W + col]) =
                    make_float2(acc[mt][ng][0] * DESCALE, acc[mt][ng][1] * DESCALE);
                *reinterpret_cast<float2*>(&Ls[(row + 8) * LS_W + col]) =
                    make_float2(acc[mt][ng][2] * DESCALE, acc[mt][ng][3] * DESCALE);
            }
        }
    }
    __syncthreads();

    // ---- router epilogue: 1 warp per token ----
    for (int t = wid; t < BM; t += (NTHREADS / 32)) {
        int gt = bm0 + t;
        if (gt >= Ntok) continue;
        const float* Lr = Ls + t * LS_W;

        float v0 = Lr[lane];
        float v1 = Lr[lane + 32];
        float v2 = Lr[lane + 64];
        float v3 = Lr[lane + 96];

        float mx = fmaxf(fmaxf(v0, v1), fmaxf(v2, v3));
#pragma unroll
        for (int off = 16; off > 0; off >>= 1)
            mx = fmaxf(mx, __shfl_xor_sync(0xffffffffu, mx, off));

        float e0 = expf(v0 - mx);
        float e1 = expf(v1 - mx);
        float e2 = expf(v2 - mx);
        float e3 = expf(v3 - mx);
        float sum = e0 + e1 + e2 + e3;
#pragma unroll
        for (int off = 16; off > 0; off >>= 1)
            sum += __shfl_xor_sync(0xffffffffu, sum, off);

        float s0 = e0 / sum, s1 = e1 / sum, s2 = e2 / sum, s3 = e3 / sum;

        float bb0 = s0 + __ldg(BIAS + lane);
        float bb1 = s1 + __ldg(BIAS + lane + 32);
        float bb2 = s2 + __ldg(BIAS + lane + 64);
        float bb3 = s3 + __ldg(BIAS + lane + 96);

        float topw[TOPK];
        int   topi[TOPK];
#pragma unroll
        for (int i = 0; i < TOPK; ++i) {
            float bv = bb0; int bi = lane;
            if (bb1 > bv) { bv = bb1; bi = lane + 32; }
            if (bb2 > bv) { bv = bb2; bi = lane + 64; }
            if (bb3 > bv) { bv = bb3; bi = lane + 96; }
#pragma unroll
            for (int off = 16; off > 0; off >>= 1) {
                float ov = __shfl_xor_sync(0xffffffffu, bv, off);
                int   oi = __shfl_xor_sync(0xffffffffu, bi, off);
                if (ov > bv || (ov == bv && oi < bi)) { bv = ov; bi = oi; }
            }
            topi[i] = bi;
            int src = bi & 31, slot = bi >> 5;
            float sv = (slot == 0) ? s0 : (slot == 1) ? s1 : (slot == 2) ? s2 : s3;
            sv = __shfl_sync(0xffffffffu, sv, src);
            topw[i] = sv;
            if (lane == src) {
                if      (slot == 0) bb0 = -INFINITY;
                else if (slot == 1) bb1 = -INFINITY;
                else if (slot == 2) bb2 = -INFINITY;
                else                bb3 = -INFINITY;
            }
        }

        float n2 = 0.f;
#pragma unroll
        for (int i = 0; i < TOPK; ++i) n2 += topw[i] * topw[i];
        float nrm = sqrtf(n2);

        if (lane == 0) {
            size_t base = (size_t)gt * TOPK;
            float4 w0 = make_float4(topw[0] / nrm, topw[1] / nrm, topw[2] / nrm, topw[3] / nrm);
            float4 w1 = make_float4(topw[4] / nrm, topw[5] / nrm, topw[6] / nrm, topw[7] / nrm);
            *reinterpret_cast<float4*>(&OUTW[base])     = w0;
            *reinterpret_cast<float4*>(&OUTW[base + 4]) = w1;
            if (writeIdx) {
                float4 i0 = make_float4((float)topi[0], (float)topi[1], (float)topi[2], (float)topi[3]);
                float4 i1 = make_float4((float)topi[4], (float)topi[5], (float)topi[6], (float)topi[7]);
                *reinterpret_cast<float4*>(&OUTI[base])     = i0;
                *reinterpret_cast<float4*>(&OUTI[base + 4]) = i1;
            }
        }
    }
}

extern "C" void kernel_launch(void* const* d_in, const int* in_sizes, int n_in,
                              void* d_out, int out_size)
{
    const float* x    = (const float*)d_in[0];
    const float* w    = (const float*)d_in[1];
    const float* bias = (const float*)d_in[2];

    const int Ntok = in_sizes[0] / D_MODEL;

    float* outw = (float*)d_out;
    int writeIdx = (out_size >= 2 * Ntok * TOPK) ? 1 : 0;
    float* outi = outw + (size_t)Ntok * TOPK;

    cudaFuncSetAttribute(moe_router_kernel,
                         cudaFuncAttributeMaxDynamicSharedMemorySize, SMEM_REQ);

    wsplit_kernel<<<(NEXP * D_MODEL / 4 + 255) / 256, 256>>>(w);
    int grid = (Ntok + BM - 1) / BM;
    moe_router_kernel<<<grid, NTHREADS, SMEM_REQ>>>(x, bias, outw, outi, writeIdx, Ntok);
}

// round 13
// speedup vs baseline: 1.1079x; 1.1079x over previous
#include <cuda_runtime.h>
#include <cuda_fp16.h>
#include <math.h>
#include <stdint.h>

#define D_MODEL 2048
#define NEXP    128
#define BM      128
#define KC      64
#define NKC     (D_MODEL / KC)    // 32
#define NTHREADS 512
#define TOPK    8

#define SAW    72                   // smem stride in halves (conflict-free ldmatrix)
#define TILEB  (128 * SAW * 2)      // 18432 B per tile
#define BUFB   (4 * TILEB)          // A_hi, A_lo, B_hi, B_lo
#define SMEM_REQ (2 * BUFB)         // 147456 B
#define LS_W   132

#define SX 64.0f
#define SW 256.0f
#define DESCALE 6.103515625e-05f    // 2^-14 exact

__device__ __half WHg[NEXP * D_MODEL];
__device__ __half WLg[NEXP * D_MODEL];

__device__ __forceinline__ uint32_t smem_u32(const void* p) {
    uint32_t a;
    asm("{ .reg .u64 t; cvta.to.shared.u64 t, %1; cvt.u32.u64 %0, t; }" : "=r"(a) : "l"(p));
    return a;
}
__device__ __forceinline__ void ldmx4(uint32_t& r0, uint32_t& r1, uint32_t& r2, uint32_t& r3,
                                      uint32_t addr) {
    asm volatile("ldmatrix.sync.aligned.m8n8.x4.shared.b16 {%0,%1,%2,%3}, [%4];"
                 : "=r"(r0), "=r"(r1), "=r"(r2), "=r"(r3) : "r"(addr));
}
__device__ __forceinline__ void mma16816(float* d, const uint32_t* a, uint32_t b0, uint32_t b1) {
    asm volatile(
        "mma.sync.aligned.m16n8k16.row.col.f32.f16.f16.f32 "
        "{%0,%1,%2,%3}, {%4,%5,%6,%7}, {%8,%9}, {%0,%1,%2,%3};"
        : "+f"(d[0]), "+f"(d[1]), "+f"(d[2]), "+f"(d[3])
        : "r"(a[0]), "r"(a[1]), "r"(a[2]), "r"(a[3]), "r"(b0), "r"(b1));
}
__device__ __forceinline__ void cpasync16(uint32_t saddr, const void* gptr) {
    asm volatile("cp.async.ca.shared.global [%0], [%1], 16;" :: "r"(saddr), "l"(gptr) : "memory");
}

__device__ __forceinline__ void split4(float4 v, float s, uint2& hi, uint2& lo) {
    float a = v.x * s, b = v.y * s, c = v.z * s, d = v.w * s;
    __half2 h01 = __floats2half2_rn(a, b);
    __half2 h23 = __floats2half2_rn(c, d);
    float2 f01 = __half22float2(h01);
    float2 f23 = __half22float2(h23);
    __half2 l01 = __floats2half2_rn(a - f01.x, b - f01.y);
    __half2 l23 = __floats2half2_rn(c - f23.x, d - f23.y);
    hi.x = *reinterpret_cast<uint32_t*>(&h01);
    hi.y = *reinterpret_cast<uint32_t*>(&h23);
    lo.x = *reinterpret_cast<uint32_t*>(&l01);
    lo.y = *reinterpret_cast<uint32_t*>(&l23);
}

// ---- kernel 0: split W once ----
__global__ void wsplit_kernel(const float* __restrict__ W) {
    int idx = blockIdx.x * blockDim.x + threadIdx.x;
    float4 v = reinterpret_cast<const float4*>(W)[idx];
    uint2 h, l;
    split4(v, SW, h, l);
    reinterpret_cast<uint2*>(WHg)[idx] = h;
    reinterpret_cast<uint2*>(WLg)[idx] = l;
}

__global__ __launch_bounds__(NTHREADS, 1)
void moe_router_kernel(const float* __restrict__ X,
                       const float* __restrict__ BIAS,
                       float* __restrict__ OUTW,
                       float* __restrict__ OUTI,
                       int writeIdx, int Ntok)
{
    extern __shared__ char sraw[];
    const uint32_t sbase = smem_u32(sraw);

    const int tid  = threadIdx.x;
    const int wid  = tid >> 5;
    const int lane = tid & 31;
    const int bm0  = blockIdx.x * BM;

    const int wm = wid >> 2;
    const int wn = wid & 3;

    const uint32_t aoff = (uint32_t)(((lane & 15) * SAW + (lane >> 4) * 8) * 2);
    const uint32_t boff = (uint32_t)((((lane & 7) + ((lane >> 4) << 3)) * SAW) * 2
                                     + ((lane >> 3) & 1) * 16);

    // A staging: 2048 float4 / 512 thr = 4 per thread
    int rA[4], cA[4];
#pragma unroll
    for (int p = 0; p < 4; ++p) {
        int idx = tid + p * NTHREADS;
        rA[p] = idx >> 4;
        cA[p] = (idx & 15) * 4;
    }
    // B staging (cp.async): 2 x 16B chunks per precision per thread
    const int rB = tid >> 2;
    const int cB = (tid & 3) * 8;

    float acc[2][4][4];
#pragma unroll
    for (int i = 0; i < 2; ++i)
#pragma unroll
        for (int j = 0; j < 4; ++j)
#pragma unroll
            for (int q = 0; q < 4; ++q)
                acc[i][j][q] = 0.f;

    // ---- prologue: stage chunk 0 ----
    float4 axr[4];
#pragma unroll
    for (int p = 0; p < 4; ++p) {
        int row = bm0 + rA[p];
        axr[p] = (row < Ntok)
            ? *reinterpret_cast<const float4*>(X + (size_t)row * D_MODEL + cA[p])
            : make_float4(0.f, 0.f, 0.f, 0.f);
    }
    {
        char* AH = sraw;
        char* AL = sraw + TILEB;
#pragma unroll
        for (int p = 0; p < 4; ++p) {
            uint32_t off = (uint32_t)(rA[p] * SAW + cA[p]) * 2;
            uint2 h, l;
            split4(axr[p], SX, h, l);
            *reinterpret_cast<uint2*>(AH + off) = h;
            *reinterpret_cast<uint2*>(AL + off) = l;
        }
        uint32_t bdst = sbase + 2 * TILEB + (uint32_t)(rB * SAW + cB) * 2;
        const __half* gH = WHg + (size_t)rB * D_MODEL + cB;
        const __half* gL = WLg + (size_t)rB * D_MODEL + cB;
        cpasync16(bdst,              gH);
        cpasync16(bdst + 64,         gH + 32);
        cpasync16(bdst + TILEB,      gL);
        cpasync16(bdst + TILEB + 64, gL + 32);
        asm volatile("cp.async.commit_group;" ::: "memory");
        asm volatile("cp.async.wait_group 0;" ::: "memory");
    }
    __syncthreads();

    for (int c = 0; c < NKC; ++c) {
        const int buf = c & 1;
        const uint32_t otherbuf = sbase + ((c + 1) & 1) * BUFB;

        // ---- issue next-chunk B cp.async + A LDG FIRST (overlap with MMAs) ----
        if (c + 1 < NKC) {
            const int k0 = (c + 1) * KC;
            uint32_t bdst = otherbuf + 2 * TILEB + (uint32_t)(rB * SAW + cB) * 2;
            const __half* gH = WHg + (size_t)rB * D_MODEL + k0 + cB;
            const __half* gL = WLg + (size_t)rB * D_MODEL + k0 + cB;
            cpasync16(bdst,              gH);
            cpasync16(bdst + 64,         gH + 32);
            cpasync16(bdst + TILEB,      gL);
            cpasync16(bdst + TILEB + 64, gL + 32);
            asm volatile("cp.async.commit_group;" ::: "memory");
#pragma unroll
            for (int p = 0; p < 4; ++p) {
                int row = bm0 + rA[p];
                axr[p] = (row < Ntok)
                    ? *reinterpret_cast<const float4*>(X + (size_t)row * D_MODEL + k0 + cA[p])
                    : make_float4(0.f, 0.f, 0.f, 0.f);
            }
        }

        // ---- compute chunk c ----
        const uint32_t bufA = sbase + buf * BUFB;
#pragma unroll
        for (int ks = 0; ks < KC / 16; ++ks) {
            const uint32_t kb = ks * 32;
            uint32_t aH[2][4], aL[2][4];
#pragma unroll
            for (int mt = 0; mt < 2; ++mt) {
                uint32_t ab = bufA + (uint32_t)((wm * 32 + mt * 16) * SAW * 2) + aoff + kb;
                ldmx4(aH[mt][0], aH[mt][1], aH[mt][2], aH[mt][3], ab);
                ldmx4(aL[mt][0], aL[mt][1], aL[mt][2], aL[mt][3], ab + TILEB);
            }
            uint32_t bh[4][2], bl[4][2];
#pragma unroll
            for (int pr = 0; pr < 2; ++pr) {
                uint32_t bb = bufA + 2 * TILEB
                            + (uint32_t)((wn * 32 + pr * 16) * SAW * 2) + boff + kb;
                ldmx4(bh[pr * 2][0], bh[pr * 2][1], bh[pr * 2 + 1][0], bh[pr * 2 + 1][1], bb);
                ldmx4(bl[pr * 2][0], bl[pr * 2][1], bl[pr * 2 + 1][0], bl[pr * 2 + 1][1], bb + TILEB);
            }
#pragma unroll
            for (int ng = 0; ng < 4; ++ng)
#pragma unroll
                for (int mt = 0; mt < 2; ++mt)
                    mma16816(acc[mt][ng], aH[mt], bh[ng][0], bh[ng][1]);
#pragma unroll
            for (int ng = 0; ng < 4; ++ng)
#pragma unroll
                for (int mt = 0; mt < 2; ++mt)
                    mma16816(acc[mt][ng], aH[mt], bl[ng][0], bl[ng][1]);
#pragma unroll
            for (int ng = 0; ng < 4; ++ng)
#pragma unroll
                for (int mt = 0; mt < 2; ++mt)
                    mma16816(acc[mt][ng], aL[mt], bh[ng][0], bh[ng][1]);
        }

        // ---- stage next A, wait B, ONE barrier ----
        if (c + 1 < NKC) {
            uint2 ah[4], al[4];
#pragma unroll
            for (int p = 0; p < 4; ++p)
                split4(axr[p], SX, ah[p], al[p]);
            char* nAH = sraw + ((c + 1) & 1) * BUFB;
            char* nAL = nAH + TILEB;
#pragma unroll
            for (int p = 0; p < 4; ++p) {
                uint32_t off = (uint32_t)(rA[p] * SAW + cA[p]) * 2;
                *reinterpret_cast<uint2*>(nAH + off) = ah[p];
                *reinterpret_cast<uint2*>(nAL + off) = al[p];
            }
            asm volatile("cp.async.wait_group 0;" ::: "memory");
            __syncthreads();
        }
    }

    // ---- logits to smem (descaled) ----
    __syncthreads();
    float* Ls = reinterpret_cast<float*>(sraw);
    {
        const int g  = lane >> 2;
        const int t2 = (lane & 3) * 2;
#pragma unroll
        for (int mt = 0; mt < 2; ++mt) {
            int row = wm * 32 + mt * 16 + g;
#pragma unroll
            for (int ng = 0; ng < 4; ++ng) {
                int col = wn * 32 + ng * 8 + t2;
                *reinterpret_cast<float2*>(&Ls[row * LS_W + col]) =
                    make_float2(acc[mt][ng][0] * DESCALE, acc[mt][ng][1] * DESCALE);
                *reinterpret_cast<float2*>(&Ls[(row + 8) * LS_W + col]) =
                    make_float2(acc[mt][ng][2] * DESCALE, acc[mt][ng][3] * DESCALE);
            }
        }
    }
    __syncthreads();

    // ---- router epilogue: 1 warp per token ----
    for (int t = wid; t < BM; t += (NTHREADS / 32)) {
        int gt = bm0 + t;
        if (gt >= Ntok) continue;
        const float* Lr = Ls + t * LS_W;

        float v0 = Lr[lane];
        float v1 = Lr[lane + 32];
        float v2 = Lr[lane + 64];
        float v3 = Lr[lane + 96];

        float mx = fmaxf(fmaxf(v0, v1), fmaxf(v2, v3));
#pragma unroll
        for (int off = 16; off > 0; off >>= 1)
            mx = fmaxf(mx, __shfl_xor_sync(0xffffffffu, mx, off));

        float e0 = expf(v0 - mx);
        float e1 = expf(v1 - mx);
        float e2 = expf(v2 - mx);
        float e3 = expf(v3 - mx);
        float sum = e0 + e1 + e2 + e3;
#pragma unroll
        for (int off = 16; off > 0; off >>= 1)
            sum += __shfl_xor_sync(0xffffffffu, sum, off);

        float s0 = e0 / sum, s1 = e1 / sum, s2 = e2 / sum, s3 = e3 / sum;

        float bb0 = s0 + __ldg(BIAS + lane);
        float bb1 = s1 + __ldg(BIAS + lane + 32);
        float bb2 = s2 + __ldg(BIAS + lane + 64);
        float bb3 = s3 + __ldg(BIAS + lane + 96);

        float topw[TOPK];
        int   topi[TOPK];
#pragma unroll
        for (int i = 0; i < TOPK; ++i) {
            float bv = bb0; int bi = lane;
            if (bb1 > bv) { bv = bb1; bi = lane + 32; }
            if (bb2 > bv) { bv = bb2; bi = lane + 64; }
            if (bb3 > bv) { bv = bb3; bi = lane + 96; }
#pragma unroll
            for (int off = 16; off > 0; off >>= 1) {
                float ov = __shfl_xor_sync(0xffffffffu, bv, off);
                int   oi = __shfl_xor_sync(0xffffffffu, bi, off);
                if (ov > bv || (ov == bv && oi < bi)) { bv = ov; bi = oi; }
            }
            topi[i] = bi;
            int src = bi & 31, slot = bi >> 5;
            float sv = (slot == 0) ? s0 : (slot == 1) ? s1 : (slot == 2) ? s2 : s3;
            sv = __shfl_sync(0xffffffffu, sv, src);
            topw[i] = sv;
            if (lane == src) {
                if      (slot == 0) bb0 = -INFINITY;
                else if (slot == 1) bb1 = -INFINITY;
                else if (slot == 2) bb2 = -INFINITY;
                else                bb3 = -INFINITY;
            }
        }

        float n2 = 0.f;
#pragma unroll
        for (int i = 0; i < TOPK; ++i) n2 += topw[i] * topw[i];
        float nrm = sqrtf(n2);

        if (lane == 0) {
            size_t base = (size_t)gt * TOPK;
            float4 w0 = make_float4(topw[0] / nrm, topw[1] / nrm, topw[2] / nrm, topw[3] / nrm);
            float4 w1 = make_float4(topw[4] / nrm, topw[5] / nrm, topw[6] / nrm, topw[7] / nrm);
            *reinterpret_cast<float4*>(&OUTW[base])     = w0;
            *reinterpret_cast<float4*>(&OUTW[base + 4]) = w1;
            if (writeIdx) {
                float4 i0 = make_float4((float)topi[0], (float)topi[1], (float)topi[2], (float)topi[3]);
                float4 i1 = make_float4((float)topi[4], (float)topi[5], (float)topi[6], (float)topi[7]);
                *reinterpret_cast<float4*>(&OUTI[base])     = i0;
                *reinterpret_cast<float4*>(&OUTI[base + 4]) = i1;
            }
        }
    }
}

extern "C" void kernel_launch(void* const* d_in, const int* in_sizes, int n_in,
                              void* d_out, int out_size)
{
    const float* x    = (const float*)d_in[0];
    const float* w    = (const float*)d_in[1];
    const float* bias = (const float*)d_in[2];

    const int Ntok = in_sizes[0] / D_MODEL;

    float* outw = (float*)d_out;
    int writeIdx = (out_size >= 2 * Ntok * TOPK) ? 1 : 0;
    float* outi = outw + (size_t)Ntok * TOPK;

    cudaFuncSetAttribute(moe_router_kernel,
                         cudaFuncAttributeMaxDynamicSharedMemorySize, SMEM_REQ);

    wsplit_kernel<<<(NEXP * D_MODEL / 4 + 255) / 256, 256>>>(w);
    int grid = (Ntok + BM - 1) / BM;
    moe_router_kernel<<<grid, NTHREADS, SMEM_REQ>>>(x, bias, outw, outi, writeIdx, Ntok);
}